// round 8
// baseline (speedup 1.0000x reference)
#include <cuda_runtime.h>
#include <cuda_bf16.h>
#include <cuda_fp16.h>
#include <math.h>
#include <stdint.h>

#define D 128
#define MAXN 50000
#define MAXE 800000
#define NBS ((MAXN + 1023) / 1024)

// ---------------- scratch ----------------
__device__ __half g_H16[MAXN * D];   // fp16 features (only consumer: gather)
__device__ float g_A1[MAXN * D];
__device__ float g_A2[MAXN * D];
__device__ float g_HM[MAXN * D];
__device__ int   g_degF[MAXN];
__device__ int   g_degR[MAXN];
__device__ int   g_offF[MAXN];
__device__ int   g_offR[MAXN];
__device__ int   g_curF[MAXN];
__device__ int   g_curR[MAXN];
__device__ float g_dF[MAXN];
__device__ float g_dR[MAXN];
__device__ int2  g_csrF[MAXE];
__device__ int2  g_csrR[MAXE];
__device__ int   g_bsF[NBS + 1];
__device__ int   g_bsR[NBS + 1];
#define WPN 8192
__device__ uint32_t g_Wp[12 * WPN];

__device__ __forceinline__ uint32_t pack_bf16(float lo_val, float hi_val) {
    uint32_t u;
    asm("cvt.rn.bf16x2.f32 %0, %1, %2;" : "=r"(u) : "f"(hi_val), "f"(lo_val));
    return u;
}
__device__ __forceinline__ void mma16(float* d, uint32_t a0, uint32_t a1, uint32_t a2,
                                      uint32_t a3, uint32_t b0, uint32_t b1) {
    asm volatile("mma.sync.aligned.m16n8k16.row.col.f32.bf16.bf16.f32 "
                 "{%0,%1,%2,%3}, {%4,%5,%6,%7}, {%8,%9}, {%0,%1,%2,%3};"
                 : "+f"(d[0]), "+f"(d[1]), "+f"(d[2]), "+f"(d[3])
                 : "r"(a0), "r"(a1), "r"(a2), "r"(a3), "r"(b0), "r"(b1));
}

// ---------------- prelude kernels ----------------
__global__ void zero_deg_kernel(int* a, int* b, int n) {
    int i = blockIdx.x * blockDim.x + threadIdx.x;
    if (i < n) { a[i] = 0; b[i] = 0; }
}

__global__ void deg_kernel(const int* __restrict__ ei, int E, int* dgF, int* dgR) {
    int e = blockIdx.x * blockDim.x + threadIdx.x;
    if (e < E) {
        atomicAdd(dgF + ei[E + e], 1);
        atomicAdd(dgR + ei[e],     1);
    }
}

__global__ void prep_kernel(const int* dgF, const int* dgR, float* dF, float* dR, int n,
                            const float* __restrict__ W1, const float* __restrict__ W2,
                            const float* __restrict__ w11, const float* __restrict__ w12,
                            const float* __restrict__ w21, const float* __restrict__ w22,
                            uint32_t* Wp) {
    int i = blockIdx.x * blockDim.x + threadIdx.x;
    if (i < n) {
        dF[i] = rsqrtf((float)dgF[i] + 1.f);
        dR[i] = rsqrtf((float)dgR[i] + 1.f);
    }
    if (i < WPN) {
        int row = i >> 6;
        int p   = i & 63;
        int k0  = 2 * p, k1 = 2 * p + 1;
        int X   = ((row >> 1) & 3) << 2;
        int dst = row * 64 + ((p & ~15) | ((p & 15) ^ X));
        const float* srcs[6];
        srcs[0] = W1; srcs[1] = W2; srcs[2] = w11; srcs[3] = w12; srcs[4] = w21; srcs[5] = w22;
#pragma unroll
        for (int wgt = 0; wgt < 6; wgt++) {
            float v0, v1;
            if (wgt < 2) {
                v0 = srcs[wgt][k0 * D + row];
                v1 = srcs[wgt][k1 * D + row];
            } else {
                v0 = srcs[wgt][row * D + k0];
                v1 = srcs[wgt][row * D + k1];
            }
            float h0 = __bfloat162float(__float2bfloat16_rn(v0));
            float h1 = __bfloat162float(__float2bfloat16_rn(v1));
            Wp[(2 * wgt + 0) * WPN + dst] = pack_bf16(v0, v1);
            Wp[(2 * wgt + 1) * WPN + dst] = pack_bf16(v0 - h0, v1 - h1);
        }
    }
}

__global__ void scan_bsum_kernel(const int* __restrict__ degF, const int* __restrict__ degR,
                                 int* bsF, int* bsR, int n) {
    __shared__ int sf[8], sr[8];
    int b = blockIdx.x, t = threadIdx.x;
    int aF = 0, aR = 0;
    int base = b * 1024;
    for (int j = t; j < 1024; j += 256) {
        int i = base + j;
        if (i < n) { aF += degF[i]; aR += degR[i]; }
    }
#pragma unroll
    for (int o = 16; o; o >>= 1) {
        aF += __shfl_down_sync(0xffffffffu, aF, o);
        aR += __shfl_down_sync(0xffffffffu, aR, o);
    }
    if ((t & 31) == 0) { sf[t >> 5] = aF; sr[t >> 5] = aR; }
    __syncthreads();
    if (t < 8) {
        aF = sf[t]; aR = sr[t];
#pragma unroll
        for (int o = 4; o; o >>= 1) {
            aF += __shfl_down_sync(0xffu, aF, o);
            aR += __shfl_down_sync(0xffu, aR, o);
        }
        if (t == 0) { bsF[b] = aF; bsR[b] = aR; }
    }
}

__global__ void scan_write_kernel(const int* __restrict__ degF, const int* __restrict__ degR,
                                  const int* __restrict__ bsF, const int* __restrict__ bsR,
                                  int* offF, int* offR, int* curF, int* curR, int n) {
    __shared__ int sF[32], sR[32];
    __shared__ int baseF, baseR;
    int b = blockIdx.x, t = threadIdx.x, lane = t & 31, w = t >> 5;
    if (t == 0) {
        int bf = 0, br = 0;
        for (int j = 0; j < b; j++) { bf += bsF[j]; br += bsR[j]; }
        baseF = bf; baseR = br;
    }
    int i = b * 1024 + t;
    int vF = (i < n) ? degF[i] : 0;
    int vR = (i < n) ? degR[i] : 0;
    int iF = vF, iR = vR;
#pragma unroll
    for (int o = 1; o < 32; o <<= 1) {
        int a = __shfl_up_sync(0xffffffffu, iF, o);
        int c = __shfl_up_sync(0xffffffffu, iR, o);
        if (lane >= o) { iF += a; iR += c; }
    }
    if (lane == 31) { sF[w] = iF; sR[w] = iR; }
    __syncthreads();
    if (w == 0) {
        int aF = sF[lane], aR = sR[lane];
#pragma unroll
        for (int o = 1; o < 32; o <<= 1) {
            int a = __shfl_up_sync(0xffffffffu, aF, o);
            int c = __shfl_up_sync(0xffffffffu, aR, o);
            if (lane >= o) { aF += a; aR += c; }
        }
        sF[lane] = aF; sR[lane] = aR;
    }
    __syncthreads();
    int pF = (w > 0) ? sF[w - 1] : 0;
    int pR = (w > 0) ? sR[w - 1] : 0;
    if (i < n) {
        int exF = baseF + pF + iF - vF;
        int exR = baseR + pR + iR - vR;
        offF[i] = exF; offR[i] = exR;
        curF[i] = exF; curR[i] = exR;
    }
}

__global__ void fill_csr_kernel(const int* __restrict__ ei, int E,
                                const float* __restrict__ dF, const float* __restrict__ dR,
                                int* curF, int* curR, int2* csrF, int2* csrR) {
    int e = blockIdx.x * blockDim.x + threadIdx.x;
    if (e >= E) return;
    int s = ei[e];
    int d = ei[E + e];
    float cf = dF[s] * dF[d];
    float cr = dR[s] * dR[d];
    int pF = atomicAdd(curF + d, 1);
    csrF[pF] = make_int2(s, __float_as_int(cf));
    int pR = atomicAdd(curR + s, 1);
    csrR[pR] = make_int2(d, __float_as_int(cr));
}

// ---------------- bf16x3 mma GEMM, 128x128 tile, 256 threads, 2 CTA/SM ----------
// GATE=0: C (=__half* H16) = Aa @ B1^T, stored fp16
// GATE=1: C (=float*) = sig(Aa@B1^T + Ab@B2^T + bias)*Aa + (1-sig)*Ab
template<int GATE>
__global__ void __launch_bounds__(256, 2)
mma_gemm(const float* __restrict__ Aa, const float* __restrict__ Ab,
         const uint32_t* __restrict__ B1h, const uint32_t* __restrict__ B1l,
         const uint32_t* __restrict__ B2h, const uint32_t* __restrict__ B2l,
         const float* __restrict__ bias, void* __restrict__ Cout, int M) {
    __shared__ uint32_t sAH[2048], sAL[2048], sBH[2048], sBL[2048];

    const int tid  = threadIdx.x;
    const int wid  = tid >> 5;
    const int lane = tid & 31;
    const int g    = lane >> 2;
    const int c    = lane & 3;
    const int wm   = wid & 3;
    const int wn   = wid >> 2;
    const int m0   = blockIdx.x * 128;
    const int nvalid = min(128, M - m0);

    float acc[2][8][4];
#pragma unroll
    for (int mt = 0; mt < 2; mt++)
#pragma unroll
        for (int nt = 0; nt < 8; nt++)
#pragma unroll
            for (int r = 0; r < 4; r++) acc[mt][nt][r] = 0.f;

    const int r0 = wm * 32 + g;
    const int nr = wn * 64 + g;

    const int NCH = GATE ? 8 : 4;
    for (int ch = 0; ch < NCH; ch++) {
        const float*    A  = (GATE && ch >= 4) ? Ab  : Aa;
        const uint32_t* Bh = (GATE && ch >= 4) ? B2h : B1h;
        const uint32_t* Bl = (GATE && ch >= 4) ? B2l : B1l;
        const int kc4 = (ch & 3) * 8;
        const int kcp = (ch & 3) * 16;
        __syncthreads();
#pragma unroll
        for (int i = 0; i < 4; i++) {
            int f   = i * 256 + tid;
            int row = f >> 3, k4 = f & 7;
            float4 v = (row < nvalid) ? ((const float4*)A)[(m0 + row) * 32 + kc4 + k4]
                                      : make_float4(0.f, 0.f, 0.f, 0.f);
            float h0 = __bfloat162float(__float2bfloat16_rn(v.x));
            float h1 = __bfloat162float(__float2bfloat16_rn(v.y));
            float h2 = __bfloat162float(__float2bfloat16_rn(v.z));
            float h3 = __bfloat162float(__float2bfloat16_rn(v.w));
            uint32_t hi0 = pack_bf16(v.x, v.y);
            uint32_t hi1 = pack_bf16(v.z, v.w);
            uint32_t lo0 = pack_bf16(v.x - h0, v.y - h1);
            uint32_t lo1 = pack_bf16(v.z - h2, v.w - h3);
            int X = ((row >> 1) & 3) << 2;
            int s = row * 16 + ((k4 * 2) ^ X);
            *(uint2*)&sAH[s] = make_uint2(hi0, hi1);
            *(uint2*)&sAL[s] = make_uint2(lo0, lo1);
        }
#pragma unroll
        for (int i = 0; i < 2; i++) {
            int f   = i * 256 + tid;
            int row = f >> 2, q4 = (f & 3) * 4;
            *(uint4*)&sBH[row * 16 + q4] = *(const uint4*)&Bh[row * 64 + kcp + q4];
            *(uint4*)&sBL[row * 16 + q4] = *(const uint4*)&Bl[row * 64 + kcp + q4];
        }
        __syncthreads();
#pragma unroll
        for (int ks = 0; ks < 2; ks++) {
            const int pc = ks * 8;
            uint32_t aH[2][4], aL[2][4];
#pragma unroll
            for (int mt = 0; mt < 2; mt++) {
                int ra = r0 + mt * 16;
                int rb = ra + 8;
                int Xa = ((ra >> 1) & 3) << 2;
                int Xb = ((rb >> 1) & 3) << 2;
                int ia0 = ra * 16 + ((pc + c) ^ Xa);
                int ib0 = rb * 16 + ((pc + c) ^ Xb);
                int ia1 = ra * 16 + ((pc + c + 4) ^ Xa);
                int ib1 = rb * 16 + ((pc + c + 4) ^ Xb);
                aH[mt][0] = sAH[ia0]; aH[mt][1] = sAH[ib0];
                aH[mt][2] = sAH[ia1]; aH[mt][3] = sAH[ib1];
                aL[mt][0] = sAL[ia0]; aL[mt][1] = sAL[ib0];
                aL[mt][2] = sAL[ia1]; aL[mt][3] = sAL[ib1];
            }
#pragma unroll
            for (int nt = 0; nt < 8; nt++) {
                int n  = nr + nt * 8;
                int Xn = ((n >> 1) & 3) << 2;
                int i0 = n * 16 + ((pc + c) ^ Xn);
                int i1 = n * 16 + ((pc + c + 4) ^ Xn);
                uint32_t bh0 = sBH[i0], bh1 = sBH[i1];
                uint32_t bl0 = sBL[i0], bl1 = sBL[i1];
#pragma unroll
                for (int mt = 0; mt < 2; mt++) {
                    mma16(acc[mt][nt], aH[mt][0], aH[mt][1], aH[mt][2], aH[mt][3], bh0, bh1);
                    mma16(acc[mt][nt], aL[mt][0], aL[mt][1], aL[mt][2], aL[mt][3], bh0, bh1);
                    mma16(acc[mt][nt], aH[mt][0], aH[mt][1], aH[mt][2], aH[mt][3], bl0, bl1);
                }
            }
        }
    }

    // epilogue: row = m0 + wm*32 + mt*16 + g + rh*8; col = wn*64 + nt*8 + c*2
#pragma unroll
    for (int mt = 0; mt < 2; mt++) {
#pragma unroll
        for (int rh = 0; rh < 2; rh++) {
            int row = m0 + wm * 32 + mt * 16 + g + rh * 8;
            if (row >= M) continue;
#pragma unroll
            for (int nt = 0; nt < 8; nt++) {
                int col = wn * 64 + nt * 8 + c * 2;
                float v0 = acc[mt][nt][rh * 2 + 0];
                float v1 = acc[mt][nt][rh * 2 + 1];
                if (!GATE) {
                    ((__half2*)Cout)[row * 64 + (col >> 1)] = __floats2half2_rn(v0, v1);
                } else {
                    float2 bb = *(const float2*)(bias + col);
                    float2 o1 = *(const float2*)(Aa + (size_t)row * D + col);
                    float2 o2 = *(const float2*)(Ab + (size_t)row * D + col);
                    float g0 = 1.f / (1.f + __expf(-(v0 + bb.x)));
                    float g1 = 1.f / (1.f + __expf(-(v1 + bb.y)));
                    float2 o;
                    o.x = g0 * o1.x + (1.f - g0) * o2.x;
                    o.y = g1 * o1.y + (1.f - g1) * o2.y;
                    *(float2*)((float*)Cout + (size_t)row * D + col) = o;
                }
            }
        }
    }
}

// ---------------- gather (fp16 features): one warp per node, both directions ------
// each lane covers 4 cols via one uint2 (4 halves) per row -> 256B/row
__global__ void gather_kernel(const __half* __restrict__ H16,
                              const int2* __restrict__ csrF, const int2* __restrict__ csrR,
                              const int* __restrict__ offF, const int* __restrict__ offR,
                              const int* __restrict__ degF, const int* __restrict__ degR,
                              const float* __restrict__ dF, const float* __restrict__ dR,
                              const float* __restrict__ bias,
                              float* __restrict__ A1, float* __restrict__ A2, int N) {
    int w = (blockIdx.x * blockDim.x + threadIdx.x) >> 5;
    int lane = threadIdx.x & 31;
    if (w >= N) return;
    const uint2* H2 = (const uint2*)H16;     // 32 uint2 per row

    float4 acc1 = make_float4(0.f, 0.f, 0.f, 0.f);
    float4 acc2 = make_float4(0.f, 0.f, 0.f, 0.f);

    int oF = offF[w], nF = degF[w];
    for (int b = 0; b < nF; b += 32) {
        int m = min(32, nF - b);
        int2 ent = (lane < m) ? csrF[oF + b + lane] : make_int2(0, 0);
        for (int j = 0; j < m; j++) {
            int   idx = __shfl_sync(0xffffffffu, ent.x, j);
            float cc  = __int_as_float(__shfl_sync(0xffffffffu, ent.y, j));
            uint2 u = H2[idx * 32 + lane];
            float2 f0 = __half22float2(*(__half2*)&u.x);
            float2 f1 = __half22float2(*(__half2*)&u.y);
            acc1.x = fmaf(f0.x, cc, acc1.x);
            acc1.y = fmaf(f0.y, cc, acc1.y);
            acc1.z = fmaf(f1.x, cc, acc1.z);
            acc1.w = fmaf(f1.y, cc, acc1.w);
        }
    }
    int oR = offR[w], nR = degR[w];
    for (int b = 0; b < nR; b += 32) {
        int m = min(32, nR - b);
        int2 ent = (lane < m) ? csrR[oR + b + lane] : make_int2(0, 0);
        for (int j = 0; j < m; j++) {
            int   idx = __shfl_sync(0xffffffffu, ent.x, j);
            float cc  = __int_as_float(__shfl_sync(0xffffffffu, ent.y, j));
            uint2 u = H2[idx * 32 + lane];
            float2 f0 = __half22float2(*(__half2*)&u.x);
            float2 f1 = __half22float2(*(__half2*)&u.y);
            acc2.x = fmaf(f0.x, cc, acc2.x);
            acc2.y = fmaf(f0.y, cc, acc2.y);
            acc2.z = fmaf(f1.x, cc, acc2.z);
            acc2.w = fmaf(f1.y, cc, acc2.w);
        }
    }
    uint2 us = H2[w * 32 + lane];
    float2 h0 = __half22float2(*(__half2*)&us.x);
    float2 h1 = __half22float2(*(__half2*)&us.y);
    float4 bb = ((const float4*)bias)[lane];
    float f2 = dF[w]; f2 *= f2;
    float r2 = dR[w]; r2 *= r2;
    float4 a1, a2;
    a1.x = fmaxf(fmaf(h0.x, f2, acc1.x) + bb.x, 0.f);
    a1.y = fmaxf(fmaf(h0.y, f2, acc1.y) + bb.y, 0.f);
    a1.z = fmaxf(fmaf(h1.x, f2, acc1.z) + bb.z, 0.f);
    a1.w = fmaxf(fmaf(h1.y, f2, acc1.w) + bb.w, 0.f);
    a2.x = fmaxf(fmaf(h0.x, r2, acc2.x) + bb.x, 0.f);
    a2.y = fmaxf(fmaf(h0.y, r2, acc2.y) + bb.y, 0.f);
    a2.z = fmaxf(fmaf(h1.x, r2, acc2.z) + bb.z, 0.f);
    a2.w = fmaxf(fmaf(h1.y, r2, acc2.w) + bb.w, 0.f);
    ((float4*)A1)[w * 32 + lane] = a1;
    ((float4*)A2)[w * 32 + lane] = a2;
}

// ---------------- driver ----------------
extern "C" void kernel_launch(void* const* d_in, const int* in_sizes, int n_in,
                              void* d_out, int out_size) {
    const float* x   = (const float*)d_in[0];
    const int*   ei  = (const int*)  d_in[1];
    const float* W1  = (const float*)d_in[2];
    const float* bc1 = (const float*)d_in[3];
    const float* W2  = (const float*)d_in[4];
    const float* bc2 = (const float*)d_in[5];
    const float* w11 = (const float*)d_in[6];
    const float* w12 = (const float*)d_in[7];
    const float* b1  = (const float*)d_in[8];
    const float* w21 = (const float*)d_in[9];
    const float* w22 = (const float*)d_in[10];
    const float* b2  = (const float*)d_in[11];

    const int N = in_sizes[0] / D;
    const int E = in_sizes[1] / 2;

    float *A1, *A2, *HM, *dF, *dR;
    __half* H16;
    int *degF, *degR, *offF, *offR, *curF, *curR, *bsF, *bsR;
    int2 *csrF, *csrR;
    uint32_t* Wp;
    cudaGetSymbolAddress((void**)&H16,  g_H16);
    cudaGetSymbolAddress((void**)&A1,   g_A1);
    cudaGetSymbolAddress((void**)&A2,   g_A2);
    cudaGetSymbolAddress((void**)&HM,   g_HM);
    cudaGetSymbolAddress((void**)&degF, g_degF);
    cudaGetSymbolAddress((void**)&degR, g_degR);
    cudaGetSymbolAddress((void**)&offF, g_offF);
    cudaGetSymbolAddress((void**)&offR, g_offR);
    cudaGetSymbolAddress((void**)&curF, g_curF);
    cudaGetSymbolAddress((void**)&curR, g_curR);
    cudaGetSymbolAddress((void**)&dF,   g_dF);
    cudaGetSymbolAddress((void**)&dR,   g_dR);
    cudaGetSymbolAddress((void**)&csrF, g_csrF);
    cudaGetSymbolAddress((void**)&csrR, g_csrR);
    cudaGetSymbolAddress((void**)&bsF,  g_bsF);
    cudaGetSymbolAddress((void**)&bsR,  g_bsR);
    cudaGetSymbolAddress((void**)&Wp,   g_Wp);

    const uint32_t* W1h  = Wp + 0 * WPN;  const uint32_t* W1l  = Wp + 1 * WPN;
    const uint32_t* W2h  = Wp + 2 * WPN;  const uint32_t* W2l  = Wp + 3 * WPN;
    const uint32_t* G11h = Wp + 4 * WPN;  const uint32_t* G11l = Wp + 5 * WPN;
    const uint32_t* G12h = Wp + 6 * WPN;  const uint32_t* G12l = Wp + 7 * WPN;
    const uint32_t* G21h = Wp + 8 * WPN;  const uint32_t* G21l = Wp + 9 * WPN;
    const uint32_t* G22h = Wp + 10 * WPN; const uint32_t* G22l = Wp + 11 * WPN;

    const int TB = 256;
    const int gN    = (N + TB - 1) / TB;
    const int gE    = (E + TB - 1) / TB;
    const int gGath = (N * 32 + TB - 1) / TB;
    const int gMma  = (N + 127) / 128;
    const int nbs   = (N + 1023) / 1024;

    zero_deg_kernel<<<gN, TB>>>(degF, degR, N);                                   // 1
    deg_kernel<<<gE, TB>>>(ei, E, degF, degR);                                    // 2
    prep_kernel<<<gN, TB>>>(degF, degR, dF, dR, N, W1, W2, w11, w12, w21, w22, Wp); // 3
    mma_gemm<0><<<gMma, TB>>>(x, nullptr, W1h, W1l, nullptr, nullptr,
                              nullptr, H16, N);                                   // 4 PROFILED
    scan_bsum_kernel<<<nbs, TB>>>(degF, degR, bsF, bsR, N);                       // 5
    scan_write_kernel<<<nbs, 1024>>>(degF, degR, bsF, bsR, offF, offR, curF, curR, N); // 6
    fill_csr_kernel<<<gE, TB>>>(ei, E, dF, dR, curF, curR, csrF, csrR);           // 7

    // ================= layer 1 =================
    gather_kernel<<<gGath, TB>>>(H16, csrF, csrR, offF, offR, degF, degR,
                                 dF, dR, bc1, A1, A2, N);
    mma_gemm<1><<<gMma, TB>>>(A1, A2, G11h, G11l, G12h, G12l, b1, HM, N);

    // ================= layer 2 =================
    mma_gemm<0><<<gMma, TB>>>(HM, nullptr, W2h, W2l, nullptr, nullptr,
                              nullptr, H16, N);
    gather_kernel<<<gGath, TB>>>(H16, csrF, csrR, offF, offR, degF, degR,
                                 dF, dR, bc2, A1, A2, N);
    mma_gemm<1><<<gMma, TB>>>(A1, A2, G21h, G21l, G22h, G22l, b2,
                              (float*)d_out, N);
}

// round 9
// speedup vs baseline: 1.4894x; 1.4894x over previous
#include <cuda_runtime.h>
#include <cuda_bf16.h>
#include <math.h>
#include <stdint.h>

#define D 128
#define MAXN 50000
#define MAXE 800000
#define NBS ((MAXN + 1023) / 1024)

// ---------------- scratch ----------------
__device__ float g_H [MAXN * D];
__device__ float g_A1[MAXN * D];
__device__ float g_A2[MAXN * D];
__device__ float g_HM[MAXN * D];
__device__ int   g_degF[MAXN];
__device__ int   g_degR[MAXN];
__device__ int   g_offF[MAXN];
__device__ int   g_offR[MAXN];
__device__ int   g_curF[MAXN];
__device__ int   g_curR[MAXN];
__device__ float g_dF[MAXN];
__device__ float g_dR[MAXN];
__device__ int2  g_csrF[MAXE];
__device__ int2  g_csrR[MAXE];
#define WPN 8192
__device__ uint32_t g_Wp[12 * WPN];

__device__ __forceinline__ uint32_t pack_bf16(float lo_val, float hi_val) {
    uint32_t u;
    asm("cvt.rn.bf16x2.f32 %0, %1, %2;" : "=r"(u) : "f"(hi_val), "f"(lo_val));
    return u;
}
__device__ __forceinline__ void mma16(float* d, uint32_t a0, uint32_t a1, uint32_t a2,
                                      uint32_t a3, uint32_t b0, uint32_t b1) {
    asm volatile("mma.sync.aligned.m16n8k16.row.col.f32.bf16.bf16.f32 "
                 "{%0,%1,%2,%3}, {%4,%5,%6,%7}, {%8,%9}, {%0,%1,%2,%3};"
                 : "+f"(d[0]), "+f"(d[1]), "+f"(d[2]), "+f"(d[3])
                 : "r"(a0), "r"(a1), "r"(a2), "r"(a3), "r"(b0), "r"(b1));
}

// ---------------- launch 1: zero degree counters + build weight planes ----------
__global__ void zw_kernel(int* dgF, int* dgR, int n,
                          const float* __restrict__ W1, const float* __restrict__ W2,
                          const float* __restrict__ w11, const float* __restrict__ w12,
                          const float* __restrict__ w21, const float* __restrict__ w22,
                          uint32_t* Wp) {
    int i = blockIdx.x * blockDim.x + threadIdx.x;
    if (i < n) { dgF[i] = 0; dgR[i] = 0; }
    if (i < WPN) {
        int row = i >> 6;
        int p   = i & 63;
        int k0  = 2 * p, k1 = 2 * p + 1;
        int X   = ((row >> 1) & 3) << 2;
        int dst = row * 64 + ((p & ~15) | ((p & 15) ^ X));
        const float* srcs[6];
        srcs[0] = W1; srcs[1] = W2; srcs[2] = w11; srcs[3] = w12; srcs[4] = w21; srcs[5] = w22;
#pragma unroll
        for (int wgt = 0; wgt < 6; wgt++) {
            float v0, v1;
            if (wgt < 2) {              // transpose [K,N] -> [N,K]
                v0 = srcs[wgt][k0 * D + row];
                v1 = srcs[wgt][k1 * D + row];
            } else {                    // gate weights already [N,K]
                v0 = srcs[wgt][row * D + k0];
                v1 = srcs[wgt][row * D + k1];
            }
            float h0 = __bfloat162float(__float2bfloat16_rn(v0));
            float h1 = __bfloat162float(__float2bfloat16_rn(v1));
            Wp[(2 * wgt + 0) * WPN + dst] = pack_bf16(v0, v1);
            Wp[(2 * wgt + 1) * WPN + dst] = pack_bf16(v0 - h0, v1 - h1);
        }
    }
}

// ---------------- launch 2: degree histogram ----------------
__global__ void deg_kernel(const int* __restrict__ ei, int E, int* dgF, int* dgR) {
    int e = blockIdx.x * blockDim.x + threadIdx.x;
    if (e < E) {
        atomicAdd(dgF + ei[E + e], 1);
        atomicAdd(dgR + ei[e],     1);
    }
}

// ---------------- launch 3: merged exclusive scan (+ dinv) -------------------
// Each block recomputes its prefix base directly from degF/degR, then does a
// local 1024-wide scan, writes off/cur, and dinv for its range.
__global__ void scan_kernel(const int* __restrict__ degF, const int* __restrict__ degR,
                            int* offF, int* offR, int* curF, int* curR,
                            float* dF, float* dR, int n) {
    __shared__ int sF[32], sR[32];
    __shared__ int baseF, baseR;
    int b = blockIdx.x, t = threadIdx.x, lane = t & 31, w = t >> 5;

    // prefix base: sum of deg over [0, b*1024)
    int aF = 0, aR = 0;
    int lim = b * 1024;
    for (int i = t; i < lim; i += 1024) { aF += degF[i]; aR += degR[i]; }
#pragma unroll
    for (int o = 16; o; o >>= 1) {
        aF += __shfl_down_sync(0xffffffffu, aF, o);
        aR += __shfl_down_sync(0xffffffffu, aR, o);
    }
    if (lane == 0) { sF[w] = aF; sR[w] = aR; }
    __syncthreads();
    if (w == 0) {
        aF = sF[lane]; aR = sR[lane];
#pragma unroll
        for (int o = 16; o; o >>= 1) {
            aF += __shfl_down_sync(0xffffffffu, aF, o);
            aR += __shfl_down_sync(0xffffffffu, aR, o);
        }
        if (lane == 0) { baseF = aF; baseR = aR; }
    }
    __syncthreads();

    // local exclusive scan
    int i = b * 1024 + t;
    int vF = (i < n) ? degF[i] : 0;
    int vR = (i < n) ? degR[i] : 0;
    int iF = vF, iR = vR;
#pragma unroll
    for (int o = 1; o < 32; o <<= 1) {
        int a = __shfl_up_sync(0xffffffffu, iF, o);
        int c = __shfl_up_sync(0xffffffffu, iR, o);
        if (lane >= o) { iF += a; iR += c; }
    }
    __syncthreads();                 // sF/sR reuse
    if (lane == 31) { sF[w] = iF; sR[w] = iR; }
    __syncthreads();
    if (w == 0) {
        int aF2 = sF[lane], aR2 = sR[lane];
#pragma unroll
        for (int o = 1; o < 32; o <<= 1) {
            int a = __shfl_up_sync(0xffffffffu, aF2, o);
            int c = __shfl_up_sync(0xffffffffu, aR2, o);
            if (lane >= o) { aF2 += a; aR2 += c; }
        }
        sF[lane] = aF2; sR[lane] = aR2;
    }
    __syncthreads();
    int pF = (w > 0) ? sF[w - 1] : 0;
    int pR = (w > 0) ? sR[w - 1] : 0;
    if (i < n) {
        int exF = baseF + pF + iF - vF;
        int exR = baseR + pR + iR - vR;
        offF[i] = exF; offR[i] = exR;
        curF[i] = exF; curR[i] = exR;
        dF[i] = rsqrtf((float)vF + 1.f);
        dR[i] = rsqrtf((float)vR + 1.f);
    }
}

// ---------------- launch 5: fill CSR lists ----------------
__global__ void fill_csr_kernel(const int* __restrict__ ei, int E,
                                const float* __restrict__ dF, const float* __restrict__ dR,
                                int* curF, int* curR, int2* csrF, int2* csrR) {
    int e = blockIdx.x * blockDim.x + threadIdx.x;
    if (e >= E) return;
    int s = ei[e];
    int d = ei[E + e];
    float cf = dF[s] * dF[d];
    float cr = dR[s] * dR[d];
    int pF = atomicAdd(curF + d, 1);
    csrF[pF] = make_int2(s, __float_as_int(cf));
    int pR = atomicAdd(curR + s, 1);
    csrR[pR] = make_int2(d, __float_as_int(cr));
}

// ---------------- bf16x3 mma GEMM, 128x128 tile, 256 threads, 2 CTA/SM ----------
// GATE=0: C[M,128] = Aa @ B1^T    GATE=1: gated combine epilogue
template<int GATE>
__global__ void __launch_bounds__(256, 2)
mma_gemm(const float* __restrict__ Aa, const float* __restrict__ Ab,
         const uint32_t* __restrict__ B1h, const uint32_t* __restrict__ B1l,
         const uint32_t* __restrict__ B2h, const uint32_t* __restrict__ B2l,
         const float* __restrict__ bias, float* __restrict__ C, int M) {
    __shared__ uint32_t sAH[2048], sAL[2048], sBH[2048], sBL[2048];

    const int tid  = threadIdx.x;
    const int wid  = tid >> 5;
    const int lane = tid & 31;
    const int g    = lane >> 2;
    const int c    = lane & 3;
    const int wm   = wid & 3;
    const int wn   = wid >> 2;
    const int m0   = blockIdx.x * 128;
    const int nvalid = min(128, M - m0);

    float acc[2][8][4];
#pragma unroll
    for (int mt = 0; mt < 2; mt++)
#pragma unroll
        for (int nt = 0; nt < 8; nt++)
#pragma unroll
            for (int r = 0; r < 4; r++) acc[mt][nt][r] = 0.f;

    const int r0 = wm * 32 + g;
    const int nr = wn * 64 + g;

    const int NCH = GATE ? 8 : 4;
    for (int ch = 0; ch < NCH; ch++) {
        const float*    A  = (GATE && ch >= 4) ? Ab  : Aa;
        const uint32_t* Bh = (GATE && ch >= 4) ? B2h : B1h;
        const uint32_t* Bl = (GATE && ch >= 4) ? B2l : B1l;
        const int kc4 = (ch & 3) * 8;
        const int kcp = (ch & 3) * 16;
        __syncthreads();
#pragma unroll
        for (int i = 0; i < 4; i++) {
            int f   = i * 256 + tid;
            int row = f >> 3, k4 = f & 7;
            float4 v = (row < nvalid) ? ((const float4*)A)[(m0 + row) * 32 + kc4 + k4]
                                      : make_float4(0.f, 0.f, 0.f, 0.f);
            float h0 = __bfloat162float(__float2bfloat16_rn(v.x));
            float h1 = __bfloat162float(__float2bfloat16_rn(v.y));
            float h2 = __bfloat162float(__float2bfloat16_rn(v.z));
            float h3 = __bfloat162float(__float2bfloat16_rn(v.w));
            uint32_t hi0 = pack_bf16(v.x, v.y);
            uint32_t hi1 = pack_bf16(v.z, v.w);
            uint32_t lo0 = pack_bf16(v.x - h0, v.y - h1);
            uint32_t lo1 = pack_bf16(v.z - h2, v.w - h3);
            int X = ((row >> 1) & 3) << 2;
            int s = row * 16 + ((k4 * 2) ^ X);
            *(uint2*)&sAH[s] = make_uint2(hi0, hi1);
            *(uint2*)&sAL[s] = make_uint2(lo0, lo1);
        }
#pragma unroll
        for (int i = 0; i < 2; i++) {
            int f   = i * 256 + tid;
            int row = f >> 2, q4 = (f & 3) * 4;
            *(uint4*)&sBH[row * 16 + q4] = *(const uint4*)&Bh[row * 64 + kcp + q4];
            *(uint4*)&sBL[row * 16 + q4] = *(const uint4*)&Bl[row * 64 + kcp + q4];
        }
        __syncthreads();
#pragma unroll
        for (int ks = 0; ks < 2; ks++) {
            const int pc = ks * 8;
            uint32_t aH[2][4], aL[2][4];
#pragma unroll
            for (int mt = 0; mt < 2; mt++) {
                int ra = r0 + mt * 16;
                int rb = ra + 8;
                int Xa = ((ra >> 1) & 3) << 2;
                int Xb = ((rb >> 1) & 3) << 2;
                int ia0 = ra * 16 + ((pc + c) ^ Xa);
                int ib0 = rb * 16 + ((pc + c) ^ Xb);
                int ia1 = ra * 16 + ((pc + c + 4) ^ Xa);
                int ib1 = rb * 16 + ((pc + c + 4) ^ Xb);
                aH[mt][0] = sAH[ia0]; aH[mt][1] = sAH[ib0];
                aH[mt][2] = sAH[ia1]; aH[mt][3] = sAH[ib1];
                aL[mt][0] = sAL[ia0]; aL[mt][1] = sAL[ib0];
                aL[mt][2] = sAL[ia1]; aL[mt][3] = sAL[ib1];
            }
#pragma unroll
            for (int nt = 0; nt < 8; nt++) {
                int n  = nr + nt * 8;
                int Xn = ((n >> 1) & 3) << 2;
                int i0 = n * 16 + ((pc + c) ^ Xn);
                int i1 = n * 16 + ((pc + c + 4) ^ Xn);
                uint32_t bh0 = sBH[i0], bh1 = sBH[i1];
                uint32_t bl0 = sBL[i0], bl1 = sBL[i1];
#pragma unroll
                for (int mt = 0; mt < 2; mt++) {
                    mma16(acc[mt][nt], aH[mt][0], aH[mt][1], aH[mt][2], aH[mt][3], bh0, bh1);
                    mma16(acc[mt][nt], aL[mt][0], aL[mt][1], aL[mt][2], aL[mt][3], bh0, bh1);
                    mma16(acc[mt][nt], aH[mt][0], aH[mt][1], aH[mt][2], aH[mt][3], bl0, bl1);
                }
            }
        }
    }

#pragma unroll
    for (int mt = 0; mt < 2; mt++) {
#pragma unroll
        for (int rh = 0; rh < 2; rh++) {
            int row = m0 + wm * 32 + mt * 16 + g + rh * 8;
            if (row >= M) continue;
#pragma unroll
            for (int nt = 0; nt < 8; nt++) {
                int col = wn * 64 + nt * 8 + c * 2;
                float v0 = acc[mt][nt][rh * 2 + 0];
                float v1 = acc[mt][nt][rh * 2 + 1];
                if (!GATE) {
                    *(float2*)(C + (size_t)row * D + col) = make_float2(v0, v1);
                } else {
                    float2 bb = *(const float2*)(bias + col);
                    float2 o1 = *(const float2*)(Aa + (size_t)row * D + col);
                    float2 o2 = *(const float2*)(Ab + (size_t)row * D + col);
                    float g0 = 1.f / (1.f + __expf(-(v0 + bb.x)));
                    float g1 = 1.f / (1.f + __expf(-(v1 + bb.y)));
                    float2 o;
                    o.x = g0 * o1.x + (1.f - g0) * o2.x;
                    o.y = g1 * o1.y + (1.f - g1) * o2.y;
                    *(float2*)(C + (size_t)row * D + col) = o;
                }
            }
        }
    }
}

// ---------------- gather: one warp per node, 2-way unrolled edge loop ------------
__global__ void gather_kernel(const float* __restrict__ H,
                              const int2* __restrict__ csrF, const int2* __restrict__ csrR,
                              const int* __restrict__ offF, const int* __restrict__ offR,
                              const int* __restrict__ degF, const int* __restrict__ degR,
                              const float* __restrict__ dF, const float* __restrict__ dR,
                              const float* __restrict__ bias,
                              float* __restrict__ A1, float* __restrict__ A2, int N) {
    int w = (blockIdx.x * blockDim.x + threadIdx.x) >> 5;
    int lane = threadIdx.x & 31;
    if (w >= N) return;
    const float4* H4 = (const float4*)H;

    float4 acc1 = make_float4(0.f, 0.f, 0.f, 0.f);
    float4 acc2 = make_float4(0.f, 0.f, 0.f, 0.f);

    int oF = offF[w], nF = degF[w];
    for (int b = 0; b < nF; b += 32) {
        int m = min(32, nF - b);
        int2 ent = (lane < m) ? csrF[oF + b + lane] : make_int2(0, 0);
        int j = 0;
        for (; j + 1 < m; j += 2) {
            int   i0 = __shfl_sync(0xffffffffu, ent.x, j);
            float c0 = __int_as_float(__shfl_sync(0xffffffffu, ent.y, j));
            int   i1 = __shfl_sync(0xffffffffu, ent.x, j + 1);
            float c1 = __int_as_float(__shfl_sync(0xffffffffu, ent.y, j + 1));
            float4 h0 = H4[i0 * 32 + lane];
            float4 h1 = H4[i1 * 32 + lane];
            acc1.x = fmaf(h0.x, c0, acc1.x); acc1.y = fmaf(h0.y, c0, acc1.y);
            acc1.z = fmaf(h0.z, c0, acc1.z); acc1.w = fmaf(h0.w, c0, acc1.w);
            acc1.x = fmaf(h1.x, c1, acc1.x); acc1.y = fmaf(h1.y, c1, acc1.y);
            acc1.z = fmaf(h1.z, c1, acc1.z); acc1.w = fmaf(h1.w, c1, acc1.w);
        }
        if (j < m) {
            int   i0 = __shfl_sync(0xffffffffu, ent.x, j);
            float c0 = __int_as_float(__shfl_sync(0xffffffffu, ent.y, j));
            float4 h0 = H4[i0 * 32 + lane];
            acc1.x = fmaf(h0.x, c0, acc1.x); acc1.y = fmaf(h0.y, c0, acc1.y);
            acc1.z = fmaf(h0.z, c0, acc1.z); acc1.w = fmaf(h0.w, c0, acc1.w);
        }
    }
    int oR = offR[w], nR = degR[w];
    for (int b = 0; b < nR; b += 32) {
        int m = min(32, nR - b);
        int2 ent = (lane < m) ? csrR[oR + b + lane] : make_int2(0, 0);
        int j = 0;
        for (; j + 1 < m; j += 2) {
            int   i0 = __shfl_sync(0xffffffffu, ent.x, j);
            float c0 = __int_as_float(__shfl_sync(0xffffffffu, ent.y, j));
            int   i1 = __shfl_sync(0xffffffffu, ent.x, j + 1);
            float c1 = __int_as_float(__shfl_sync(0xffffffffu, ent.y, j + 1));
            float4 h0 = H4[i0 * 32 + lane];
            float4 h1 = H4[i1 * 32 + lane];
            acc2.x = fmaf(h0.x, c0, acc2.x); acc2.y = fmaf(h0.y, c0, acc2.y);
            acc2.z = fmaf(h0.z, c0, acc2.z); acc2.w = fmaf(h0.w, c0, acc2.w);
            acc2.x = fmaf(h1.x, c1, acc2.x); acc2.y = fmaf(h1.y, c1, acc2.y);
            acc2.z = fmaf(h1.z, c1, acc2.z); acc2.w = fmaf(h1.w, c1, acc2.w);
        }
        if (j < m) {
            int   i0 = __shfl_sync(0xffffffffu, ent.x, j);
            float c0 = __int_as_float(__shfl_sync(0xffffffffu, ent.y, j));
            float4 h0 = H4[i0 * 32 + lane];
            acc2.x = fmaf(h0.x, c0, acc2.x); acc2.y = fmaf(h0.y, c0, acc2.y);
            acc2.z = fmaf(h0.z, c0, acc2.z); acc2.w = fmaf(h0.w, c0, acc2.w);
        }
    }
    float4 hn = H4[w * 32 + lane];
    float4 bb = ((const float4*)bias)[lane];
    float f2 = dF[w]; f2 *= f2;
    float r2 = dR[w]; r2 *= r2;
    float4 a1, a2;
    a1.x = fmaxf(fmaf(hn.x, f2, acc1.x) + bb.x, 0.f);
    a1.y = fmaxf(fmaf(hn.y, f2, acc1.y) + bb.y, 0.f);
    a1.z = fmaxf(fmaf(hn.z, f2, acc1.z) + bb.z, 0.f);
    a1.w = fmaxf(fmaf(hn.w, f2, acc1.w) + bb.w, 0.f);
    a2.x = fmaxf(fmaf(hn.x, r2, acc2.x) + bb.x, 0.f);
    a2.y = fmaxf(fmaf(hn.y, r2, acc2.y) + bb.y, 0.f);
    a2.z = fmaxf(fmaf(hn.z, r2, acc2.z) + bb.z, 0.f);
    a2.w = fmaxf(fmaf(hn.w, r2, acc2.w) + bb.w, 0.f);
    ((float4*)A1)[w * 32 + lane] = a1;
    ((float4*)A2)[w * 32 + lane] = a2;
}

// ---------------- driver ----------------
extern "C" void kernel_launch(void* const* d_in, const int* in_sizes, int n_in,
                              void* d_out, int out_size) {
    const float* x   = (const float*)d_in[0];
    const int*   ei  = (const int*)  d_in[1];
    const float* W1  = (const float*)d_in[2];
    const float* bc1 = (const float*)d_in[3];
    const float* W2  = (const float*)d_in[4];
    const float* bc2 = (const float*)d_in[5];
    const float* w11 = (const float*)d_in[6];
    const float* w12 = (const float*)d_in[7];
    const float* b1  = (const float*)d_in[8];
    const float* w21 = (const float*)d_in[9];
    const float* w22 = (const float*)d_in[10];
    const float* b2  = (const float*)d_in[11];

    const int N = in_sizes[0] / D;
    const int E = in_sizes[1] / 2;

    float *H, *A1, *A2, *HM, *dF, *dR;
    int *degF, *degR, *offF, *offR, *curF, *curR;
    int2 *csrF, *csrR;
    uint32_t* Wp;
    cudaGetSymbolAddress((void**)&H,    g_H);
    cudaGetSymbolAddress((void**)&A1,   g_A1);
    cudaGetSymbolAddress((void**)&A2,   g_A2);
    cudaGetSymbolAddress((void**)&HM,   g_HM);
    cudaGetSymbolAddress((void**)&degF, g_degF);
    cudaGetSymbolAddress((void**)&degR, g_degR);
    cudaGetSymbolAddress((void**)&offF, g_offF);
    cudaGetSymbolAddress((void**)&offR, g_offR);
    cudaGetSymbolAddress((void**)&curF, g_curF);
    cudaGetSymbolAddress((void**)&curR, g_curR);
    cudaGetSymbolAddress((void**)&dF,   g_dF);
    cudaGetSymbolAddress((void**)&dR,   g_dR);
    cudaGetSymbolAddress((void**)&csrF, g_csrF);
    cudaGetSymbolAddress((void**)&csrR, g_csrR);
    cudaGetSymbolAddress((void**)&Wp,   g_Wp);

    const uint32_t* W1h  = Wp + 0 * WPN;  const uint32_t* W1l  = Wp + 1 * WPN;
    const uint32_t* W2h  = Wp + 2 * WPN;  const uint32_t* W2l  = Wp + 3 * WPN;
    const uint32_t* G11h = Wp + 4 * WPN;  const uint32_t* G11l = Wp + 5 * WPN;
    const uint32_t* G12h = Wp + 6 * WPN;  const uint32_t* G12l = Wp + 7 * WPN;
    const uint32_t* G21h = Wp + 8 * WPN;  const uint32_t* G21l = Wp + 9 * WPN;
    const uint32_t* G22h = Wp + 10 * WPN; const uint32_t* G22l = Wp + 11 * WPN;

    const int TB = 256;
    const int gN    = (N + TB - 1) / TB;
    const int gE    = (E + TB - 1) / TB;
    const int gGath = (N * 32 + TB - 1) / TB;
    const int gMma  = (N + 127) / 128;
    const int nbs   = (N + 1023) / 1024;

    zw_kernel<<<gN, TB>>>(degF, degR, N, W1, W2, w11, w12, w21, w22, Wp);        // 1
    deg_kernel<<<gE, TB>>>(ei, E, degF, degR);                                   // 2
    scan_kernel<<<nbs, 1024>>>(degF, degR, offF, offR, curF, curR, dF, dR, N);   // 3
    mma_gemm<0><<<gMma, TB>>>(x, nullptr, W1h, W1l, nullptr, nullptr,
                              nullptr, H, N);                                    // 4 PROFILED
    fill_csr_kernel<<<gE, TB>>>(ei, E, dF, dR, curF, curR, csrF, csrR);          // 5

    // ================= layer 1 =================
    gather_kernel<<<gGath, TB>>>(H, csrF, csrR, offF, offR, degF, degR,
                                 dF, dR, bc1, A1, A2, N);
    mma_gemm<1><<<gMma, TB>>>(A1, A2, G11h, G11l, G12h, G12l, b1, HM, N);

    // ================= layer 2 =================
    mma_gemm<0><<<gMma, TB>>>(HM, nullptr, W2h, W2l, nullptr, nullptr,
                              nullptr, H, N);
    gather_kernel<<<gGath, TB>>>(H, csrF, csrR, offF, offR, degF, degR,
                                 dF, dR, bc2, A1, A2, N);
    mma_gemm<1><<<gMma, TB>>>(A1, A2, G21h, G21l, G22h, G22l, b2,
                              (float*)d_out, N);
}